// round 4
// baseline (speedup 1.0000x reference)
#include <cuda_runtime.h>
#include <stdint.h>

#define CIN  16
#define COUT 32
#define KNB  27
#define HMAX 300000

// scratch (device globals — no runtime allocation allowed)
__device__ float  g_xT[(size_t)HMAX * CIN];            // [h][i], 19.2 MB
__device__ float2 g_wpack[KNB * CIN * (COUT / 2)];     // [k][i][opair]
__device__ float  g_sum[COUT];
__device__ float  g_sqs[COUT];
__device__ float2 g_ab[COUT];                          // (scale, bias) after BN finalize

typedef unsigned long long ull;

__device__ __forceinline__ void fma2(ull& d, ull a, ull b) {
    asm("fma.rn.f32x2 %0, %1, %2, %0;" : "+l"(d) : "l"(a), "l"(b));
}
__device__ __forceinline__ ull pack2(float v) {
    ull r; asm("mov.b64 %0, {%1, %1};" : "=l"(r) : "f"(v)); return r;
}
__device__ __forceinline__ void unpack2(ull v, float& lo, float& hi) {
    asm("mov.b64 {%0, %1}, %2;" : "=f"(lo), "=f"(hi) : "l"(v));
}

__global__ void k_init() {
    int t = threadIdx.x;
    if (t < COUT) { g_sum[t] = 0.f; g_sqs[t] = 0.f; }
}

// x[16][H] -> xT[H][16] so each neighbor gather is one contiguous 64B row
__global__ void k_transpose(const float* __restrict__ x, int H) {
    int h = blockIdx.x * blockDim.x + threadIdx.x;
    if (h >= H) return;
    float v[CIN];
#pragma unroll
    for (int i = 0; i < CIN; i++) v[i] = x[(size_t)i * H + h];
    float4* dst = (float4*)(g_xT + (size_t)h * CIN);
    dst[0] = make_float4(v[0],  v[1],  v[2],  v[3]);
    dst[1] = make_float4(v[4],  v[5],  v[6],  v[7]);
    dst[2] = make_float4(v[8],  v[9],  v[10], v[11]);
    dst[3] = make_float4(v[12], v[13], v[14], v[15]);
}

// w[o][i][k] -> g_wpack[k][i][op] = float2(w[2op][i][k], w[2op+1][i][k])
__global__ void k_pack(const float* __restrict__ w) {
    int e = blockIdx.x * blockDim.x + threadIdx.x;   // 27*256 = 6912 exactly
    int k  = e / (CIN * COUT / 2);
    int r  = e % (CIN * COUT / 2);
    int i  = r / (COUT / 2);
    int op = r % (COUT / 2);
    float w0 = w[(2 * op)     * CIN * KNB + i * KNB + k];
    float w1 = w[(2 * op + 1) * CIN * KNB + i * KNB + k];
    g_wpack[e] = make_float2(w0, w1);
}

// Main conv: one thread = one h, 32 outputs as 16 packed f32x2 accumulators.
// Weights live in dynamic shared as float2 (output-pair packed) -> LDS.128,
// all lanes hit the same address -> broadcast (conflict-free).
// NOTE: neigh arrives as int32 on device (harness downcasts the reference's
// int64) — reading it as int64 was the round-3 illegal-access bug.
__global__ void __launch_bounds__(256) k_conv(const int* __restrict__ neigh,
                                              float* __restrict__ out, int H) {
    extern __shared__ unsigned char smem[];
    ulonglong2* wsh  = (ulonglong2*)smem;            // 3456 * 16B = 55296 B
    float*      part = (float*)(smem + 55296);       // 8 warps * 64 floats

    int tid = threadIdx.x;
    for (int t = tid; t < KNB * CIN * 8; t += 256)   // 3456
        wsh[t] = ((const ulonglong2*)g_wpack)[t];
    __syncthreads();

    int h = blockIdx.x * 256 + tid;
    ull acc[16];
#pragma unroll
    for (int j = 0; j < 16; j++) acc[j] = 0ull;

    if (h < H) {
        const int* nb = neigh + (size_t)h * KNB;
        const float4* xt = (const float4*)g_xT;
#pragma unroll 1
        for (int k = 0; k < KNB; k++) {
            int idx = nb[k];
            float4 a0, a1, a2, a3;
            if (idx >= 0 && idx < H) {
                const float4* p = xt + (size_t)idx * 4;
                a0 = p[0]; a1 = p[1]; a2 = p[2]; a3 = p[3];
            } else {
                a0 = a1 = a2 = a3 = make_float4(0.f, 0.f, 0.f, 0.f);
            }
            float xv[16] = {a0.x, a0.y, a0.z, a0.w,  a1.x, a1.y, a1.z, a1.w,
                            a2.x, a2.y, a2.z, a2.w,  a3.x, a3.y, a3.z, a3.w};
            const ulonglong2* wrow = wsh + k * (CIN * 8);
#pragma unroll
            for (int i = 0; i < CIN; i++) {
                ull xd = pack2(xv[i]);
#pragma unroll
                for (int j = 0; j < 8; j++) {
                    ulonglong2 wp = wrow[i * 8 + j];
                    fma2(acc[2 * j],     wp.x, xd);   // outputs (4j,   4j+1)
                    fma2(acc[2 * j + 1], wp.y, xd);   // outputs (4j+2, 4j+3)
                }
            }
        }
    }

    float y[32];
#pragma unroll
    for (int op = 0; op < 16; op++) unpack2(acc[op], y[2 * op], y[2 * op + 1]);

    if (h < H) {
#pragma unroll
        for (int o = 0; o < 32; o++) out[(size_t)o * H + h] = y[o];
    }

    // fused BN partial sums: warp shuffle reduce -> shared -> 64 atomics/CTA
    int lane = tid & 31, warp = tid >> 5;
#pragma unroll
    for (int o = 0; o < 32; o++) {
        float s = (h < H) ? y[o] : 0.f;
        float q = s * s;
#pragma unroll
        for (int off = 16; off > 0; off >>= 1) {
            s += __shfl_xor_sync(0xffffffffu, s, off);
            q += __shfl_xor_sync(0xffffffffu, q, off);
        }
        if (lane == 0) { part[warp * 64 + o] = s; part[warp * 64 + 32 + o] = q; }
    }
    __syncthreads();
    if (tid < 64) {
        float s = 0.f;
#pragma unroll
        for (int wp = 0; wp < 8; wp++) s += part[wp * 64 + tid];
        if (tid < 32) atomicAdd(&g_sum[tid], s);
        else          atomicAdd(&g_sqs[tid - 32], s);
    }
}

__global__ void k_fin(const float* __restrict__ gamma, const float* __restrict__ beta, int H) {
    int o = threadIdx.x;
    if (o >= COUT) return;
    float invH = 1.f / (float)H;
    float mean = g_sum[o] * invH;
    float var  = g_sqs[o] * invH - mean * mean;
    float inv  = rsqrtf(var + 1e-5f);
    float a = gamma[o] * inv;
    g_ab[o] = make_float2(a, beta[o] - mean * a);
}

__global__ void k_norm(float* __restrict__ out, int H) {
    int o = blockIdx.y;
    float2 ab = g_ab[o];
    float* base = out + (size_t)o * H;
    int n4 = H >> 2;
    int i4 = blockIdx.x * blockDim.x + threadIdx.x;
    if (i4 < n4) {
        float4* p = (float4*)base + i4;
        float4 v = *p;
        v.x = v.x * ab.x + ab.y;
        v.y = v.y * ab.x + ab.y;
        v.z = v.z * ab.x + ab.y;
        v.w = v.w * ab.x + ab.y;
        *p = v;
    }
    if (blockIdx.x == 0 && threadIdx.x < (H & 3)) {
        int hh = (n4 << 2) + threadIdx.x;
        base[hh] = base[hh] * ab.x + ab.y;
    }
}

extern "C" void kernel_launch(void* const* d_in, const int* in_sizes, int n_in,
                              void* d_out, int out_size) {
    const float* data_in = (const float*)d_in[0];
    const float* weight  = (const float*)d_in[1];
    const float* gamma   = (const float*)d_in[2];
    const float* beta    = (const float*)d_in[3];
    const int*   neigh   = (const int*)d_in[4];
    int H = in_sizes[0] / CIN;
    float* out = (float*)d_out;

    cudaFuncSetAttribute(k_conv, cudaFuncAttributeMaxDynamicSharedMemorySize, 57344);

    k_init<<<1, 64>>>();
    int hb = (H + 255) / 256;
    k_transpose<<<hb, 256>>>(data_in, H);
    k_pack<<<27, 256>>>(weight);
    k_conv<<<hb, 256, 57344>>>(neigh, out, H);
    k_fin<<<1, 32>>>(gamma, beta, H);
    dim3 gn((H / 4 + 255) / 256, 32);
    k_norm<<<gn, 256>>>(out, H);
}

// round 5
// speedup vs baseline: 1.5433x; 1.5433x over previous
#include <cuda_runtime.h>
#include <stdint.h>

#define CIN   16
#define COUT  32
#define KNB   27
#define HMAX  300032            // padded to 256-multiple

// scratch (device globals — no runtime allocation)
__device__ float  g_xT[(size_t)HMAX * CIN];          // [h][i]  19.2 MB
__device__ int    g_nT[KNB][HMAX];                   // k-major neigh, 32.4 MB
__device__ float2 g_wpack[KNB * CIN * (COUT / 2)];   // [k][i][opair]
__device__ float  g_sum[COUT];
__device__ float  g_sqs[COUT];
__device__ float2 g_ab[COUT];

typedef unsigned long long ull;

__device__ __forceinline__ void fma2(ull& d, ull a, ull b) {
    asm("fma.rn.f32x2 %0, %1, %2, %0;" : "+l"(d) : "l"(a), "l"(b));
}
__device__ __forceinline__ ull pack2(float v) {
    ull r; asm("mov.b64 %0, {%1, %1};" : "=l"(r) : "f"(v)); return r;
}
__device__ __forceinline__ void unpack2(ull v, float& lo, float& hi) {
    asm("mov.b64 {%0, %1}, %2;" : "=f"(lo), "=f"(hi) : "l"(v));
}
__device__ __forceinline__ void cp16(uint32_t dst, const void* src) {
    asm volatile("cp.async.cg.shared.global [%0], [%1], 16;" :: "r"(dst), "l"(src) : "memory");
}
__device__ __forceinline__ void cp_commit() {
    asm volatile("cp.async.commit_group;" ::: "memory");
}
template <int N>
__device__ __forceinline__ void cp_wait() {
    asm volatile("cp.async.wait_group %0;" :: "n"(N) : "memory");
}

__global__ void k_init() {
    int t = threadIdx.x;
    if (t < COUT) { g_sum[t] = 0.f; g_sqs[t] = 0.f; }
}

// prep: x[16][H] -> xT[h][16] (64B rows), neigh[h][k] -> nT[k][h]; pad h>=H
__global__ void k_prep(const float* __restrict__ x, const int* __restrict__ neigh, int H) {
    int h = blockIdx.x * 256 + threadIdx.x;
    if (h >= HMAX) return;
    float4* dst = (float4*)(g_xT + (size_t)h * CIN);
    if (h < H) {
        float v[CIN];
#pragma unroll
        for (int i = 0; i < CIN; i++) v[i] = x[(size_t)i * H + h];
        dst[0] = make_float4(v[0],  v[1],  v[2],  v[3]);
        dst[1] = make_float4(v[4],  v[5],  v[6],  v[7]);
        dst[2] = make_float4(v[8],  v[9],  v[10], v[11]);
        dst[3] = make_float4(v[12], v[13], v[14], v[15]);
        const int* nb = neigh + (size_t)h * KNB;
#pragma unroll
        for (int k = 0; k < KNB; k++) g_nT[k][h] = nb[k];
    } else {
        float4 z = make_float4(0.f, 0.f, 0.f, 0.f);
        dst[0] = z; dst[1] = z; dst[2] = z; dst[3] = z;
#pragma unroll
        for (int k = 0; k < KNB; k++) g_nT[k][h] = -1;
    }
}

// w[o][i][k] -> g_wpack[k][i][op] = (w[2op][i][k], w[2op+1][i][k])
__global__ void k_pack(const float* __restrict__ w) {
    int e = blockIdx.x * blockDim.x + threadIdx.x;   // 27*256 = 6912 exactly
    int k  = e / (CIN * COUT / 2);
    int r  = e % (CIN * COUT / 2);
    int i  = r / (COUT / 2);
    int op = r % (COUT / 2);
    g_wpack[e] = make_float2(w[(2 * op)     * CIN * KNB + i * KNB + k],
                             w[(2 * op + 1) * CIN * KNB + i * KNB + k]);
}

// smem layout (bytes):
//   [0, 55296)        weights: ulonglong2 wsh[27][16][8]
//   [55296, 96256)    stage: 4 warps x 2 bufs x 64 rows x 80B
//   [96256, 97280)    BN partials: 4 warps x 64 floats
#define SM_W     0
#define SM_STG   55296
#define SM_PART  96256
#define SM_TOTAL 97280
#define ROWW     20              // stage row stride in words (80B, conflict-free)

// 128 threads, 2 h per thread (warp covers 64 h), CTA covers 256 h.
__global__ void __launch_bounds__(128, 2) k_conv(float* __restrict__ out, int H) {
    extern __shared__ unsigned char smem[];
    ulonglong2* wsh  = (ulonglong2*)(smem + SM_W);
    float*      part = (float*)(smem + SM_PART);

    int tid  = threadIdx.x;
    int lane = tid & 31, w = tid >> 5;

    // load packed weights (3456 x 16B)
    for (int t = tid; t < KNB * CIN * 8; t += 128)
        wsh[t] = ((const ulonglong2*)g_wpack)[t];
    __syncthreads();

    int wb = blockIdx.x * 256 + w * 64;              // warp's 64-h block
    float* stg = (float*)(smem + SM_STG) + w * (2 * 64 * ROWW);
    uint32_t stg_u32 = (uint32_t)__cvta_generic_to_shared(stg);

    int rowq = lane >> 2;                            // 0..7
    int q    = lane & 3;                             // quarter (16B)

    // issue gather for k into buffer b
    auto issue = [&](int k, int b) {
        const int* nk = g_nT[k];
        uint32_t base = stg_u32 + (uint32_t)(b * 64 * ROWW * 4) + q * 16;
#pragma unroll
        for (int t = 0; t < 8; t++) {
            int row = t * 8 + rowq;
            int idx = nk[wb + row];
            uint32_t dst = base + row * (ROWW * 4);
            if (idx >= 0) {
                cp16(dst, g_xT + (size_t)idx * CIN + q * 4);
            } else {
                float4 z = make_float4(0.f, 0.f, 0.f, 0.f);
                *(float4*)((unsigned char*)stg + (dst - stg_u32)) = z;
            }
        }
        cp_commit();
    };

    ull accA[16], accB[16];
#pragma unroll
    for (int j = 0; j < 16; j++) { accA[j] = 0ull; accB[j] = 0ull; }

    issue(0, 0);

#pragma unroll 1
    for (int k = 0; k < KNB; k++) {
        if (k + 1 < KNB) { issue(k + 1, (k + 1) & 1); cp_wait<1>(); }
        else             { cp_wait<0>(); }
        __syncwarp();

        const float* buf = stg + (k & 1) * 64 * ROWW;
#pragma unroll
        for (int c = 0; c < 4; c++) {
            float4 xa = *(const float4*)(buf + lane * ROWW + c * 4);
            float4 xb = *(const float4*)(buf + (lane + 32) * ROWW + c * 4);
            float va[4] = {xa.x, xa.y, xa.z, xa.w};
            float vb[4] = {xb.x, xb.y, xb.z, xb.w};
#pragma unroll
            for (int ii = 0; ii < 4; ii++) {
                int i = c * 4 + ii;
                ull xda = pack2(va[ii]);
                ull xdb = pack2(vb[ii]);
                const ulonglong2* wrow = wsh + (k * CIN + i) * 8;
#pragma unroll
                for (int j = 0; j < 8; j++) {
                    ulonglong2 wp = wrow[j];
                    fma2(accA[2 * j],     wp.x, xda);
                    fma2(accA[2 * j + 1], wp.y, xda);
                    fma2(accB[2 * j],     wp.x, xdb);
                    fma2(accB[2 * j + 1], wp.y, xdb);
                }
            }
        }
        __syncwarp();                                // before buf reuse
    }

    // epilogue: store y, accumulate BN partials (per output-pair to cap regs)
    int h0 = wb + lane, h1 = wb + lane + 32;
    bool v0 = h0 < H, v1 = h1 < H;
#pragma unroll
    for (int op = 0; op < 16; op++) {
        float a0, a1, b0, b1;
        unpack2(accA[op], a0, a1);
        unpack2(accB[op], b0, b1);
        int o0 = 2 * op, o1 = 2 * op + 1;
        if (v0) { out[(size_t)o0 * H + h0] = a0; out[(size_t)o1 * H + h0] = a1; }
        if (v1) { out[(size_t)o0 * H + h1] = b0; out[(size_t)o1 * H + h1] = b1; }
        float s0 = (v0 ? a0 : 0.f) + (v1 ? b0 : 0.f);
        float s1 = (v0 ? a1 : 0.f) + (v1 ? b1 : 0.f);
        float q0 = (v0 ? a0 * a0 : 0.f) + (v1 ? b0 * b0 : 0.f);
        float q1 = (v0 ? a1 * a1 : 0.f) + (v1 ? b1 * b1 : 0.f);
#pragma unroll
        for (int off = 16; off > 0; off >>= 1) {
            s0 += __shfl_xor_sync(0xffffffffu, s0, off);
            s1 += __shfl_xor_sync(0xffffffffu, s1, off);
            q0 += __shfl_xor_sync(0xffffffffu, q0, off);
            q1 += __shfl_xor_sync(0xffffffffu, q1, off);
        }
        if (lane == 0) {
            part[w * 64 + o0]      = s0;
            part[w * 64 + o1]      = s1;
            part[w * 64 + 32 + o0] = q0;
            part[w * 64 + 32 + o1] = q1;
        }
    }
    __syncthreads();
    if (tid < 64) {
        float s = part[tid] + part[64 + tid] + part[128 + tid] + part[192 + tid];
        if (tid < 32) atomicAdd(&g_sum[tid], s);
        else          atomicAdd(&g_sqs[tid - 32], s);
    }
}

__global__ void k_fin(const float* __restrict__ gamma, const float* __restrict__ beta, int H) {
    int o = threadIdx.x;
    if (o >= COUT) return;
    float invH = 1.f / (float)H;
    float mean = g_sum[o] * invH;
    float var  = g_sqs[o] * invH - mean * mean;
    float inv  = rsqrtf(var + 1e-5f);
    float a = gamma[o] * inv;
    g_ab[o] = make_float2(a, beta[o] - mean * a);
}

__global__ void k_norm(float* __restrict__ out, int H) {
    int o = blockIdx.y;
    float2 ab = g_ab[o];
    float* base = out + (size_t)o * H;
    int n4 = H >> 2;
    int i4 = blockIdx.x * blockDim.x + threadIdx.x;
    if (i4 < n4) {
        float4* p = (float4*)base + i4;
        float4 v = *p;
        v.x = v.x * ab.x + ab.y;
        v.y = v.y * ab.x + ab.y;
        v.z = v.z * ab.x + ab.y;
        v.w = v.w * ab.x + ab.y;
        *p = v;
    }
    if (blockIdx.x == 0 && threadIdx.x < (H & 3)) {
        int hh = (n4 << 2) + threadIdx.x;
        base[hh] = base[hh] * ab.x + ab.y;
    }
}

extern "C" void kernel_launch(void* const* d_in, const int* in_sizes, int n_in,
                              void* d_out, int out_size) {
    const float* data_in = (const float*)d_in[0];
    const float* weight  = (const float*)d_in[1];
    const float* gamma   = (const float*)d_in[2];
    const float* beta    = (const float*)d_in[3];
    const int*   neigh   = (const int*)d_in[4];
    int H = in_sizes[0] / CIN;
    float* out = (float*)d_out;

    cudaFuncSetAttribute(k_conv, cudaFuncAttributeMaxDynamicSharedMemorySize, SM_TOTAL);

    k_init<<<1, 64>>>();
    k_prep<<<HMAX / 256, 256>>>(data_in, neigh, H);
    k_pack<<<27, 256>>>(weight);
    k_conv<<<(H + 255) / 256, 128, SM_TOTAL>>>(out, H);
    k_fin<<<1, 32>>>(gamma, beta, H);
    dim3 gn((H / 4 + 255) / 256, 32);
    k_norm<<<gn, 256>>>(out, H);
}

// round 9
// speedup vs baseline: 4.4094x; 2.8572x over previous
#include <cuda_runtime.h>
#include <cuda_fp16.h>
#include <stdint.h>

#define CIN   16
#define COUT  32
#define KNB   27
#define HMAX  300032
#define TILEM 128
#define NTHR  256

// ---------------- device globals ----------------
__device__ uint4  g_xh4[(size_t)HMAX * 2];   // x rows as f16 [h][16], 32B each (9.6 MB)
__device__ uint4  g_wB[1760];                // B image [n=o][kc], stride 880B, 16B-aligned
__device__ float  g_sum[COUT], g_sqs[COUT];
__device__ float2 g_ab[COUT];

// ---------------- smem layout (bytes) ----------------
#define SM_B     0                           // 32 * 880 = 28160
#define SM_N     28160                       // neigh tile: 128*27*4 = 13824
#define SM_STG   41984                       // 8 warps * 2 bufs * 16 rows * 48B = 12288
#define SM_PART  54272                       // 8 * 64 * 4 = 2048
#define SM_TOTAL 56320
#define ROWB     48                          // stage row stride (16B-aligned, conflict-free)

__device__ __forceinline__ uint32_t smem_u32(const void* p) {
    uint32_t a;
    asm("{ .reg .u64 t; cvta.to.shared.u64 t, %1; cvt.u32.u64 %0, t; }" : "=r"(a) : "l"(p));
    return a;
}
__device__ __forceinline__ void cp16(uint32_t dst, const void* src) {
    asm volatile("cp.async.cg.shared.global [%0], [%1], 16;" :: "r"(dst), "l"(src) : "memory");
}
__device__ __forceinline__ void zero16(uint32_t dst) {
    asm volatile("st.shared.v4.b32 [%0], {%1, %1, %1, %1};" :: "r"(dst), "r"(0) : "memory");
}
__device__ __forceinline__ void cp_commit() { asm volatile("cp.async.commit_group;" ::: "memory"); }
template <int N> __device__ __forceinline__ void cp_wait() {
    asm volatile("cp.async.wait_group %0;" :: "n"(N) : "memory");
}
__device__ __forceinline__ uint32_t lds32(uint32_t a) {
    uint32_t v; asm volatile("ld.shared.b32 %0, [%1];" : "=r"(v) : "r"(a)); return v;
}
__device__ __forceinline__ void ldmA(uint32_t& a0, uint32_t& a1, uint32_t& a2, uint32_t& a3, uint32_t addr) {
    asm volatile("ldmatrix.sync.aligned.m8n8.x4.shared.b16 {%0,%1,%2,%3}, [%4];"
                 : "=r"(a0), "=r"(a1), "=r"(a2), "=r"(a3) : "r"(addr));
}
__device__ __forceinline__ void mma16816(float* c, uint32_t a0, uint32_t a1, uint32_t a2, uint32_t a3,
                                         uint32_t b0, uint32_t b1) {
    asm volatile("mma.sync.aligned.m16n8k16.row.col.f32.f16.f16.f32 "
                 "{%0,%1,%2,%3}, {%4,%5,%6,%7}, {%8,%9}, {%0,%1,%2,%3};"
                 : "+f"(c[0]), "+f"(c[1]), "+f"(c[2]), "+f"(c[3])
                 : "r"(a0), "r"(a1), "r"(a2), "r"(a3), "r"(b0), "r"(b1));
}

// ---------------- prep kernels ----------------
__global__ void k_init() {
    int t = threadIdx.x;
    if (t < COUT) { g_sum[t] = 0.f; g_sqs[t] = 0.f; }
}

__global__ void k_xprep(const float* __restrict__ x, int H) {
    int h = blockIdx.x * 256 + threadIdx.x;
    if (h >= HMAX) return;
    __half2 v[8];
    if (h < H) {
#pragma unroll
        for (int i = 0; i < 8; i++)
            v[i] = __floats2half2_rn(x[(size_t)(2 * i) * H + h], x[(size_t)(2 * i + 1) * H + h]);
    } else {
#pragma unroll
        for (int i = 0; i < 8; i++) v[i] = __floats2half2_rn(0.f, 0.f);
    }
    uint4* dst = g_xh4 + (size_t)h * 2;
    dst[0] = *(uint4*)&v[0];
    dst[1] = *(uint4*)&v[4];
}

// B[n][kc] = w[n][i=kc%16][k=kc/16], kc<432, zero-pad to 440
__global__ void k_wprep(const float* __restrict__ w) {
    int e = blockIdx.x * 256 + threadIdx.x;   // 32*440 = 14080
    if (e >= 32 * 440) return;
    int n = e / 440, kc = e % 440;
    float v = 0.f;
    if (kc < 432) { int i = kc & 15, k = kc >> 4; v = w[n * 432 + i * 27 + k]; }
    ((__half*)g_wB)[e] = __float2half_rn(v);
}

// ---------------- main HMMA kernel ----------------
__global__ void __launch_bounds__(NTHR) k_conv(const int* __restrict__ neigh,
                                               float* __restrict__ out, int H) {
    extern __shared__ char smem[];
    uint32_t sb = smem_u32(smem);
    int tid = threadIdx.x, lane = tid & 31, w = tid >> 5;
    int q = lane & 3, r4 = lane >> 2;

    // prologue: B image + neigh tile via cp.async
    for (int j = tid; j < 1760; j += NTHR)           // 28160 B
        cp16(sb + SM_B + j * 16, g_wB + j);
    {
        size_t nlimit = (size_t)H * KNB * 4;
        size_t nbase  = (size_t)blockIdx.x * (TILEM * KNB * 4);
        const char* src = (const char*)neigh;
        for (int j = tid; j < 864; j += NTHR) {
            size_t off = nbase + (size_t)j * 16;
            uint32_t dst = sb + SM_N + j * 16;
            if (off + 16 <= nlimit) {
                cp16(dst, src + off);
            } else {
#pragma unroll
                for (int c = 0; c < 4; c++) {
                    int vv = (off + c * 4 + 4 <= nlimit) ? *(const int*)(src + off + c * 4) : -1;
                    asm volatile("st.shared.b32 [%0], %1;" :: "r"(dst + c * 4), "r"(vv) : "memory");
                }
            }
        }
    }
    cp_commit();
    cp_wait<0>();
    __syncthreads();

    // gather geometry: lane -> (row grow, 16B half ghalf)
    int grow = lane >> 1, ghalf = lane & 1;
    long hbase = (long)blockIdx.x * TILEM;
    int wr = w * 16;
    long grh = hbase + wr + grow;
    bool rowok = grh < (long)H;
    const int* nsh = (const int*)(smem + SM_N) + (wr + grow) * KNB;
    uint32_t stw = sb + SM_STG + w * (2 * 16 * ROWB);
    uint32_t gdst0 = stw + grow * ROWB + (ghalf << 4);
    uint32_t lmaddr = stw + (lane & 15) * ROWB + (lane >> 4) * 16;

    uint32_t bb[4];
#pragma unroll
    for (int nt = 0; nt < 4; nt++)
        bb[nt] = sb + SM_B + (uint32_t)((nt * 8 + r4) * 880 + q * 4);

    float c[4][4];
#pragma unroll
    for (int nt = 0; nt < 4; nt++)
#pragma unroll
        for (int j = 0; j < 4; j++) c[nt][j] = 0.f;

    // issue gather for step k into its buffer
    auto issue = [&](int k) {
        uint32_t dst = gdst0 + (k & 1) * (16 * ROWB);
        int idx = rowok ? nsh[k] : -1;
        if ((unsigned)idx < (unsigned)H)
            cp16(dst, (const char*)g_xh4 + ((size_t)(unsigned)idx << 5) + (ghalf << 4));
        else
            zero16(dst);
        cp_commit();
    };

    issue(0);
#pragma unroll 1
    for (int k = 0; k < KNB; k++) {
        if (k + 1 < KNB) { issue(k + 1); cp_wait<1>(); }
        else             { cp_wait<0>(); }
        __syncwarp();
        uint32_t a0, a1, a2, a3;
        ldmA(a0, a1, a2, a3, lmaddr + (k & 1) * (16 * ROWB));
#pragma unroll
        for (int nt = 0; nt < 4; nt++) {
            uint32_t boff = bb[nt] + (uint32_t)k * 32;
            uint32_t b0 = lds32(boff);
            uint32_t b1 = lds32(boff + 16);
            mma16816(c[nt], a0, a1, a2, a3, b0, b1);
        }
        __syncwarp();
    }

    // epilogue: direct gmem stores + BN partials
    float* part = (float*)(smem + SM_PART);
    long h  = hbase + wr + r4;
    long h8 = h + 8;
    bool v0 = h < (long)H, v8 = h8 < (long)H;
#pragma unroll
    for (int nt = 0; nt < 4; nt++) {
        int o0 = nt * 8 + 2 * q;
        if (v0) { out[(size_t)o0 * H + h]       = c[nt][0];
                  out[(size_t)(o0 + 1) * H + h] = c[nt][1]; }
        if (v8) { out[(size_t)o0 * H + h8]       = c[nt][2];
                  out[(size_t)(o0 + 1) * H + h8] = c[nt][3]; }
        float s0 = (v0 ? c[nt][0] : 0.f) + (v8 ? c[nt][2] : 0.f);
        float s1 = (v0 ? c[nt][1] : 0.f) + (v8 ? c[nt][3] : 0.f);
        float q0 = (v0 ? c[nt][0] * c[nt][0] : 0.f) + (v8 ? c[nt][2] * c[nt][2] : 0.f);
        float q1 = (v0 ? c[nt][1] * c[nt][1] : 0.f) + (v8 ? c[nt][3] * c[nt][3] : 0.f);
#pragma unroll
        for (int off = 4; off < 32; off <<= 1) {   // reduce over lanes sharing q
            s0 += __shfl_xor_sync(0xffffffffu, s0, off);
            s1 += __shfl_xor_sync(0xffffffffu, s1, off);
            q0 += __shfl_xor_sync(0xffffffffu, q0, off);
            q1 += __shfl_xor_sync(0xffffffffu, q1, off);
        }
        if (r4 == 0) {
            part[w * 64 + o0]          = s0;
            part[w * 64 + o0 + 1]      = s1;
            part[w * 64 + 32 + o0]     = q0;
            part[w * 64 + 32 + o0 + 1] = q1;
        }
    }
    __syncthreads();
    if (tid < 64) {
        float s = 0.f;
#pragma unroll
        for (int wp = 0; wp < 8; wp++) s += part[wp * 64 + tid];
        if (tid < 32) atomicAdd(&g_sum[tid], s);
        else          atomicAdd(&g_sqs[tid - 32], s);
    }
}

// ---------------- BN finalize + normalize ----------------
__global__ void k_fin(const float* __restrict__ gamma, const float* __restrict__ beta, int H) {
    int o = threadIdx.x;
    if (o >= COUT) return;
    float invH = 1.f / (float)H;
    float mean = g_sum[o] * invH;
    float var  = g_sqs[o] * invH - mean * mean;
    float inv  = rsqrtf(var + 1e-5f);
    float a = gamma[o] * inv;
    g_ab[o] = make_float2(a, beta[o] - mean * a);
}

__global__ void k_norm(float* __restrict__ out, int H) {
    int o = blockIdx.y;
    float2 ab = g_ab[o];
    float* base = out + (size_t)o * H;
    int n4 = H >> 2;
    int i4 = blockIdx.x * blockDim.x + threadIdx.x;
    if (i4 < n4) {
        float4* p = (float4*)base + i4;
        float4 v = *p;
        v.x = v.x * ab.x + ab.y;
        v.y = v.y * ab.x + ab.y;
        v.z = v.z * ab.x + ab.y;
        v.w = v.w * ab.x + ab.y;
        *p = v;
    }
    if (blockIdx.x == 0 && threadIdx.x < (H & 3)) {
        int hh = (n4 << 2) + threadIdx.x;
        base[hh] = base[hh] * ab.x + ab.y;
    }
}

extern "C" void kernel_launch(void* const* d_in, const int* in_sizes, int n_in,
                              void* d_out, int out_size) {
    const float* data_in = (const float*)d_in[0];
    const float* weight  = (const float*)d_in[1];
    const float* gamma   = (const float*)d_in[2];
    const float* beta    = (const float*)d_in[3];
    const int*   neigh   = (const int*)d_in[4];
    int H = in_sizes[0] / CIN;
    float* out = (float*)d_out;
    int ntiles = (H + TILEM - 1) / TILEM;

    cudaFuncSetAttribute(k_conv, cudaFuncAttributeMaxDynamicSharedMemorySize, SM_TOTAL);

    k_init<<<1, 64>>>();
    k_xprep<<<HMAX / 256, 256>>>(data_in, H);
    k_wprep<<<(32 * 440 + 255) / 256, 256>>>(weight);
    k_conv<<<ntiles, NTHR, SM_TOTAL>>>(neigh, out, H);
    k_fin<<<1, 32>>>(gamma, beta, H);
    dim3 gn((H / 4 + 255) / 256, 32);
    k_norm<<<gn, 256>>>(out, H);
}